// round 1
// baseline (speedup 1.0000x reference)
#include <cuda_runtime.h>
#include <math.h>

#define D_MODEL 1024
#define NHEAD 16
#define HDIM 64
#define SEQ 2048
#define NBATCH 2
#define NROWS (NBATCH * SEQ)          // 4096
#define EPS_V 1e-6f

// ---------------- scratch (device globals; no allocation allowed) -----------
__device__ float g_q[NROWS * D_MODEL];    // elu(q)+1
__device__ float g_k[NROWS * D_MODEL];    // elu(k)+1
__device__ float g_v[NROWS * D_MODEL];
__device__ float g_att[NROWS * D_MODEL];
__device__ float g_kv[NBATCH * NHEAD * HDIM * HDIM];  // per (b,h): kf^T @ v  [64x64]
__device__ float g_ksum[NBATCH * NHEAD * HDIM];       // per (b,h): sum_j kf_j

// ---------------- SGEMM: C[M,N] = A[M,K] @ W[N,K]^T + bias, optional elu+1 ---
// 128x128 block tile, BK=16, 8x8 per thread, 256 threads.
template <int ACT>
__global__ __launch_bounds__(256, 2)
void sgemm_nt(const float* __restrict__ A, const float* __restrict__ W,
              const float* __restrict__ bias, float* __restrict__ C,
              int M, int N, int K)
{
    __shared__ __align__(16) float As[16][128];
    __shared__ __align__(16) float Bs[16][128];

    const int bm = blockIdx.y * 128;
    const int bn = blockIdx.x * 128;
    const int tid = threadIdx.x;
    const int tx = tid & 15;        // col group
    const int ty = tid >> 4;        // row group

    float acc[8][8];
#pragma unroll
    for (int i = 0; i < 8; ++i)
#pragma unroll
        for (int j = 0; j < 8; ++j) acc[i][j] = 0.f;

    const int lr = tid >> 2;            // 0..63
    const int lc = (tid & 3) << 2;      // 0,4,8,12

    for (int k0 = 0; k0 < K; k0 += 16) {
#pragma unroll
        for (int p = 0; p < 2; ++p) {
            const int row = lr + p * 64;
            float4 a = *(const float4*)(A + (size_t)(bm + row) * K + k0 + lc);
            As[lc + 0][row] = a.x; As[lc + 1][row] = a.y;
            As[lc + 2][row] = a.z; As[lc + 3][row] = a.w;
            float4 b = *(const float4*)(W + (size_t)(bn + row) * K + k0 + lc);
            Bs[lc + 0][row] = b.x; Bs[lc + 1][row] = b.y;
            Bs[lc + 2][row] = b.z; Bs[lc + 3][row] = b.w;
        }
        __syncthreads();

#pragma unroll
        for (int kk = 0; kk < 16; ++kk) {
            float4 a0 = *(const float4*)(&As[kk][ty * 8]);
            float4 a1 = *(const float4*)(&As[kk][ty * 8 + 4]);
            float4 b0 = *(const float4*)(&Bs[kk][tx * 8]);
            float4 b1 = *(const float4*)(&Bs[kk][tx * 8 + 4]);
            float ra[8] = {a0.x, a0.y, a0.z, a0.w, a1.x, a1.y, a1.z, a1.w};
            float rb[8] = {b0.x, b0.y, b0.z, b0.w, b1.x, b1.y, b1.z, b1.w};
#pragma unroll
            for (int i = 0; i < 8; ++i)
#pragma unroll
                for (int j = 0; j < 8; ++j)
                    acc[i][j] = fmaf(ra[i], rb[j], acc[i][j]);
        }
        __syncthreads();
    }

    const int colBase = bn + tx * 8;
    float4 bs0 = *(const float4*)(bias + colBase);
    float4 bs1 = *(const float4*)(bias + colBase + 4);
    float bv[8] = {bs0.x, bs0.y, bs0.z, bs0.w, bs1.x, bs1.y, bs1.z, bs1.w};

#pragma unroll
    for (int i = 0; i < 8; ++i) {
        const int row = bm + ty * 8 + i;
        float o[8];
#pragma unroll
        for (int j = 0; j < 8; ++j) {
            float v = acc[i][j] + bv[j];
            if (ACT) v = (v > 0.f) ? (v + 1.f) : __expf(v);   // elu(v)+1
            o[j] = v;
        }
        float* cp = C + (size_t)row * N + colBase;
        *(float4*)(cp)     = make_float4(o[0], o[1], o[2], o[3]);
        *(float4*)(cp + 4) = make_float4(o[4], o[5], o[6], o[7]);
    }
}

// ---------------- zero the kv / ksum accumulators ---------------------------
__global__ void zero_kv_kernel()
{
    const int i = blockIdx.x * blockDim.x + threadIdx.x;
    if (i < NBATCH * NHEAD * HDIM * HDIM) g_kv[i] = 0.f;
    if (i < NBATCH * NHEAD * HDIM)        g_ksum[i] = 0.f;
}

// ---------------- kv = kf^T @ v per (b,h), split-K over sequence ------------
// grid: (32 bh, 8 splits), 256 threads; each block does 256 sequence rows.
__global__ __launch_bounds__(256)
void kv_kernel()
{
    const int bh = blockIdx.x;
    const int split = blockIdx.y;
    const int b = bh >> 4, h = bh & 15;
    const int j0 = b * SEQ + split * 256;

    const float* Kp = g_k + (size_t)j0 * D_MODEL + h * HDIM;
    const float* Vp = g_v + (size_t)j0 * D_MODEL + h * HDIM;

    __shared__ __align__(16) float ks[8][64];
    __shared__ __align__(16) float vs[8][64];

    const int tid = threadIdx.x;
    const int eg = tid & 15, dg = tid >> 4;
    const int e0 = eg * 4, d0 = dg * 4;

    float acc[4][4];
#pragma unroll
    for (int i = 0; i < 4; ++i)
#pragma unroll
        for (int j = 0; j < 4; ++j) acc[i][j] = 0.f;
    float sacc[4] = {0.f, 0.f, 0.f, 0.f};

    for (int it = 0; it < 32; ++it) {
        const int rbase = it * 8;
        if (tid < 128) {
            const int r = tid >> 4, c = (tid & 15) * 4;
            *(float4*)&ks[r][c] = *(const float4*)(Kp + (size_t)(rbase + r) * D_MODEL + c);
        } else {
            const int t = tid - 128;
            const int r = t >> 4, c = (t & 15) * 4;
            *(float4*)&vs[r][c] = *(const float4*)(Vp + (size_t)(rbase + r) * D_MODEL + c);
        }
        __syncthreads();
#pragma unroll
        for (int r = 0; r < 8; ++r) {
            float4 kd4 = *(const float4*)&ks[r][d0];
            float4 ve4 = *(const float4*)&vs[r][e0];
            float kd[4] = {kd4.x, kd4.y, kd4.z, kd4.w};
            float ve[4] = {ve4.x, ve4.y, ve4.z, ve4.w};
#pragma unroll
            for (int i = 0; i < 4; ++i)
#pragma unroll
                for (int j = 0; j < 4; ++j)
                    acc[i][j] = fmaf(kd[i], ve[j], acc[i][j]);
            if (eg == 0) {
#pragma unroll
                for (int i = 0; i < 4; ++i) sacc[i] += kd[i];
            }
        }
        __syncthreads();
    }

    float* kvp = g_kv + (size_t)bh * HDIM * HDIM;
#pragma unroll
    for (int i = 0; i < 4; ++i)
#pragma unroll
        for (int j = 0; j < 4; ++j)
            atomicAdd(&kvp[(d0 + i) * HDIM + e0 + j], acc[i][j]);
    if (eg == 0) {
#pragma unroll
        for (int i = 0; i < 4; ++i)
            atomicAdd(&g_ksum[bh * HDIM + d0 + i], sacc[i]);
    }
}

// ---------------- attended = (qf @ kv) / max(qf . ksum, eps) ----------------
// grid: (32 row-tiles of 64, 32 bh), 256 threads; each thread -> 4x4 outputs.
__global__ __launch_bounds__(256)
void attend_kernel()
{
    const int tile = blockIdx.x;
    const int bh = blockIdx.y;
    const int b = bh >> 4, h = bh & 15;
    const int row0 = b * SEQ + tile * 64;

    __shared__ __align__(16) float kvs[64][64];
    __shared__ __align__(16) float qs[64][64];
    __shared__ float ksum_s[64];

    const int tid = threadIdx.x;

    const float* kvp = g_kv + (size_t)bh * HDIM * HDIM;
    for (int i = tid; i < 1024; i += 256)
        ((float4*)kvs)[i] = ((const float4*)kvp)[i];
    if (tid < 64) ksum_s[tid] = g_ksum[bh * HDIM + tid];

    const float* Qp = g_q + (size_t)row0 * D_MODEL + h * HDIM;
    for (int i = tid; i < 1024; i += 256) {
        const int r = i >> 4, c = (i & 15) * 4;
        *(float4*)&qs[r][c] = *(const float4*)(Qp + (size_t)r * D_MODEL + c);
    }
    __syncthreads();

    const int cg = tid & 15, rg = tid >> 4;
    const int c0 = cg * 4, r0 = rg * 4;

    float num[4][4];
#pragma unroll
    for (int i = 0; i < 4; ++i)
#pragma unroll
        for (int j = 0; j < 4; ++j) num[i][j] = 0.f;
    float den[4] = {0.f, 0.f, 0.f, 0.f};

    for (int d = 0; d < 64; ++d) {
        float qv[4];
#pragma unroll
        for (int i = 0; i < 4; ++i) qv[i] = qs[r0 + i][d];
        float4 kv4 = *(const float4*)&kvs[d][c0];
        float kva[4] = {kv4.x, kv4.y, kv4.z, kv4.w};
        const float kd = ksum_s[d];
#pragma unroll
        for (int i = 0; i < 4; ++i) {
#pragma unroll
            for (int j = 0; j < 4; ++j)
                num[i][j] = fmaf(qv[i], kva[j], num[i][j]);
            den[i] = fmaf(qv[i], kd, den[i]);
        }
    }

    float* Op = g_att + (size_t)row0 * D_MODEL + h * HDIM;
#pragma unroll
    for (int i = 0; i < 4; ++i) {
        const float inv = 1.f / fmaxf(den[i], EPS_V);
        *(float4*)(Op + (size_t)(r0 + i) * D_MODEL + c0) =
            make_float4(num[i][0] * inv, num[i][1] * inv,
                        num[i][2] * inv, num[i][3] * inv);
    }
}

// ---------------- launch ----------------------------------------------------
extern "C" void kernel_launch(void* const* d_in, const int* in_sizes, int n_in,
                              void* d_out, int out_size)
{
    const float* x  = (const float*)d_in[0];
    const float* wq = (const float*)d_in[1];
    const float* bq = (const float*)d_in[2];
    const float* wk = (const float*)d_in[3];
    const float* bk = (const float*)d_in[4];
    const float* wv = (const float*)d_in[5];
    const float* bv = (const float*)d_in[6];
    const float* wo = (const float*)d_in[7];
    const float* bo = (const float*)d_in[8];
    float* out = (float*)d_out;

    const int M = in_sizes[0] / D_MODEL;   // 4096

    float *qp, *kp, *vp, *ap;
    cudaGetSymbolAddress((void**)&qp, g_q);
    cudaGetSymbolAddress((void**)&kp, g_k);
    cudaGetSymbolAddress((void**)&vp, g_v);
    cudaGetSymbolAddress((void**)&ap, g_att);

    dim3 gridP(D_MODEL / 128, M / 128);  // (8, 32)

    sgemm_nt<1><<<gridP, 256>>>(x, wq, bq, qp, M, D_MODEL, D_MODEL);
    sgemm_nt<1><<<gridP, 256>>>(x, wk, bk, kp, M, D_MODEL, D_MODEL);
    sgemm_nt<0><<<gridP, 256>>>(x, wv, bv, vp, M, D_MODEL, D_MODEL);

    zero_kv_kernel<<<(NBATCH * NHEAD * HDIM * HDIM + 255) / 256, 256>>>();
    kv_kernel<<<dim3(NBATCH * NHEAD, 8), 256>>>();
    attend_kernel<<<dim3(SEQ / 64, NBATCH * NHEAD), 256>>>();

    sgemm_nt<0><<<gridP, 256>>>(ap, wo, bo, out, M, D_MODEL, D_MODEL);
}

// round 3
// speedup vs baseline: 2.5147x; 2.5147x over previous
#include <cuda_runtime.h>
#include <cuda_bf16.h>
#include <cstdint>
#include <math.h>

#define D_MODEL 1024
#define NHEAD 16
#define HDIM 64
#define SEQ 2048
#define NBATCH 2
#define NROWS (NBATCH * SEQ)          // 4096
#define EPS_V 1e-6f

// ---------------- scratch (device globals; no allocation allowed) -----------
__device__ float g_q[NROWS * D_MODEL];    // elu(q)+1
__device__ float g_k[NROWS * D_MODEL];    // elu(k)+1
__device__ float g_v[NROWS * D_MODEL];
__device__ float g_att[NROWS * D_MODEL];
__device__ float g_kv[NBATCH * NHEAD * HDIM * HDIM];
__device__ float g_ksum[NBATCH * NHEAD * HDIM];

__device__ __forceinline__ uint32_t smem_u32(const void* p) {
    uint32_t a;
    asm("{ .reg .u64 t; cvta.to.shared.u64 t, %1; cvt.u32.u64 %0, t; }"
        : "=r"(a) : "l"(p));
    return a;
}

__device__ __forceinline__ void ldsm4(uint32_t* r, uint32_t addr) {
    asm volatile("ldmatrix.sync.aligned.m8n8.x4.shared.b16 {%0,%1,%2,%3}, [%4];"
                 : "=r"(r[0]), "=r"(r[1]), "=r"(r[2]), "=r"(r[3]) : "r"(addr));
}

__device__ __forceinline__ void mma16816(float* c, const uint32_t* a,
                                         uint32_t b0, uint32_t b1) {
    asm volatile(
        "mma.sync.aligned.m16n8k16.row.col.f32.bf16.bf16.f32 "
        "{%0,%1,%2,%3}, {%4,%5,%6,%7}, {%8,%9}, {%0,%1,%2,%3};"
        : "+f"(c[0]), "+f"(c[1]), "+f"(c[2]), "+f"(c[3])
        : "r"(a[0]), "r"(a[1]), "r"(a[2]), "r"(a[3]), "r"(b0), "r"(b1));
}

// ======================= bf16 3-term split GEMM (mma.sync) ===================
// C[M,N] = A[M,K] @ W[N,K]^T + bias   (optional elu+1 epilogue)
// BM=BN=128, BK=64 fp32. 8 warps (2 M x 4 N), warp tile 64x32.
// smem: 4 planes (A_hi, A_lo, W_hi, W_lo), each 128 rows x 64 bf16 = 128B rows,
// SW128 swizzle. Single buffer + register prefetch.
#define BM 128
#define BN 128
#define BKF 64
#define PLANE_B 16384
#define GEMM_SMEM (4 * PLANE_B)   // 65536

template <int ACT>
__global__ __launch_bounds__(256, 1)
void gemm_mma(const float* __restrict__ A, const float* __restrict__ W,
              const float* __restrict__ bias, float* __restrict__ C,
              int M, int N, int K)
{
    extern __shared__ __align__(1024) char smem[];
    const uint32_t sb = smem_u32(smem);
    const uint32_t AH = sb, AL = sb + PLANE_B, WH = sb + 2 * PLANE_B,
                   WL = sb + 3 * PLANE_B;

    const int tid = threadIdx.x;
    const int lane = tid & 31, wid = tid >> 5;
    const int wm = wid >> 2, wn = wid & 3;
    const int bm = blockIdx.y * BM, bn = blockIdx.x * BN;

    // ---- gmem load / smem store indexing (split loader) ----
    const int r0 = tid >> 4;          // 0..15
    const int c4 = tid & 15;          // float4 col
    const float* Ab = A + (size_t)(bm + r0) * K + c4 * 4;
    const float* Wb = W + (size_t)(bn + r0) * K + c4 * 4;
    const uint32_t stxor = (uint32_t)((c4 * 8) ^ ((r0 & 7) << 4));

    // ---- ldmatrix addressing ----
    // A fragment (16x16): lanes0-7 rows0-7 b0 | 8-15 rows8-15 b0 | 16-23 rows0-7 b16 | 24-31 rows8-15 b16
    const int arow_l = (lane & 15);
    const uint32_t akb = (uint32_t)((lane >> 4) * 16);
    // B fragment pair (16n x 16k): lanes0-7 n0-7 b0 | 8-15 n0-7 b16 | 16-23 n8-15 b0 | 24-31 n8-15 b16
    const int brow_l = (lane & 7) + ((lane >> 4) << 3);
    const uint32_t bkb = (uint32_t)(((lane >> 3) & 1) * 16);

    uint32_t abase[4], axor[4];
#pragma unroll
    for (int mt = 0; mt < 4; ++mt) {
        const int r = wm * 64 + mt * 16 + arow_l;
        abase[mt] = (uint32_t)(r * 128);
        axor[mt] = (uint32_t)((r & 7) << 4);
    }
    uint32_t bbase[2], bxor[2];
#pragma unroll
    for (int p = 0; p < 2; ++p) {
        const int r = wn * 32 + p * 16 + brow_l;
        bbase[p] = (uint32_t)(r * 128);
        bxor[p] = (uint32_t)((r & 7) << 4);
    }

    float acc[4][4][4];
#pragma unroll
    for (int i = 0; i < 4; ++i)
#pragma unroll
        for (int j = 0; j < 4; ++j)
#pragma unroll
            for (int d = 0; d < 4; ++d) acc[i][j][d] = 0.f;

    float4 av[8], wv[8];
#pragma unroll
    for (int i = 0; i < 8; ++i) {
        av[i] = *(const float4*)(Ab + (size_t)(16 * i) * K);
        wv[i] = *(const float4*)(Wb + (size_t)(16 * i) * K);
    }

    const int NCHUNK = K / BKF;
    for (int c = 0; c < NCHUNK; ++c) {
        // ---- split fp32 -> (hi,lo) bf16 and store swizzled ----
#pragma unroll
        for (int i = 0; i < 8; ++i) {
            const uint32_t off = (uint32_t)((r0 + 16 * i) * 128) + stxor;
            {
                uint32_t bx = __float_as_uint(av[i].x), by = __float_as_uint(av[i].y);
                uint32_t bz = __float_as_uint(av[i].z), bw = __float_as_uint(av[i].w);
                uint32_t h0 = __byte_perm(bx, by, 0x7632);
                uint32_t h1 = __byte_perm(bz, bw, 0x7632);
                float lx = av[i].x - __uint_as_float(bx & 0xFFFF0000u);
                float ly = av[i].y - __uint_as_float(by & 0xFFFF0000u);
                float lz = av[i].z - __uint_as_float(bz & 0xFFFF0000u);
                float lw = av[i].w - __uint_as_float(bw & 0xFFFF0000u);
                uint32_t l0, l1;
                asm("cvt.rn.bf16x2.f32 %0, %1, %2;" : "=r"(l0) : "f"(ly), "f"(lx));
                asm("cvt.rn.bf16x2.f32 %0, %1, %2;" : "=r"(l1) : "f"(lw), "f"(lz));
                asm volatile("st.shared.v2.b32 [%0], {%1, %2};"
                             :: "r"(AH + off), "r"(h0), "r"(h1) : "memory");
                asm volatile("st.shared.v2.b32 [%0], {%1, %2};"
                             :: "r"(AL + off), "r"(l0), "r"(l1) : "memory");
            }
            {
                uint32_t bx = __float_as_uint(wv[i].x), by = __float_as_uint(wv[i].y);
                uint32_t bz = __float_as_uint(wv[i].z), bw = __float_as_uint(wv[i].w);
                uint32_t h0 = __byte_perm(bx, by, 0x7632);
                uint32_t h1 = __byte_perm(bz, bw, 0x7632);
                float lx = wv[i].x - __uint_as_float(bx & 0xFFFF0000u);
                float ly = wv[i].y - __uint_as_float(by & 0xFFFF0000u);
                float lz = wv[i].z - __uint_as_float(bz & 0xFFFF0000u);
                float lw = wv[i].w - __uint_as_float(bw & 0xFFFF0000u);
                uint32_t l0, l1;
                asm("cvt.rn.bf16x2.f32 %0, %1, %2;" : "=r"(l0) : "f"(ly), "f"(lx));
                asm("cvt.rn.bf16x2.f32 %0, %1, %2;" : "=r"(l1) : "f"(lw), "f"(lz));
                asm volatile("st.shared.v2.b32 [%0], {%1, %2};"
                             :: "r"(WH + off), "r"(h0), "r"(h1) : "memory");
                asm volatile("st.shared.v2.b32 [%0], {%1, %2};"
                             :: "r"(WL + off), "r"(l0), "r"(l1) : "memory");
            }
        }
        __syncthreads();

        // ---- prefetch next chunk while computing this one ----
        if (c + 1 < NCHUNK) {
            const float* Ac = Ab + (c + 1) * BKF;
            const float* Wc = Wb + (c + 1) * BKF;
#pragma unroll
            for (int i = 0; i < 8; ++i) {
                av[i] = *(const float4*)(Ac + (size_t)(16 * i) * K);
                wv[i] = *(const float4*)(Wc + (size_t)(16 * i) * K);
            }
        }

        // ---- 4 k16-steps x (16 tiles x 3 terms) ----
#pragma unroll
        for (int ks = 0; ks < 4; ++ks) {
            uint32_t ah[4][4], al[4][4], bh[2][4], bl[2][4];
#pragma unroll
            for (int mt = 0; mt < 4; ++mt) {
                const uint32_t t = ((uint32_t)(ks * 32) + akb) ^ axor[mt];
                ldsm4(ah[mt], AH + abase[mt] + t);
                ldsm4(al[mt], AL + abase[mt] + t);
            }
#pragma unroll
            for (int p = 0; p < 2; ++p) {
                const uint32_t t = ((uint32_t)(ks * 32) + bkb) ^ bxor[p];
                ldsm4(bh[p], WH + bbase[p] + t);
                ldsm4(bl[p], WL + bbase[p] + t);
            }
#pragma unroll
            for (int mt = 0; mt < 4; ++mt)
#pragma unroll
                for (int nt = 0; nt < 4; ++nt) {
                    const int p = nt >> 1, q = (nt & 1) * 2;
                    mma16816(acc[mt][nt], ah[mt], bh[p][q], bh[p][q + 1]);
                    mma16816(acc[mt][nt], ah[mt], bl[p][q], bl[p][q + 1]);
                    mma16816(acc[mt][nt], al[mt], bh[p][q], bh[p][q + 1]);
                }
        }
        __syncthreads();
    }

    // ---- epilogue ----
    const int erow = bm + wm * 64 + (lane >> 2);
    const int ecol0 = bn + wn * 32 + (lane & 3) * 2;
#pragma unroll
    for (int nt = 0; nt < 4; ++nt) {
        const int col = ecol0 + nt * 8;
        const float b0 = bias[col], b1 = bias[col + 1];
#pragma unroll
        for (int mt = 0; mt < 4; ++mt) {
#pragma unroll
            for (int h = 0; h < 2; ++h) {
                const int row = erow + mt * 16 + h * 8;
                float v0 = acc[mt][nt][2 * h] + b0;
                float v1 = acc[mt][nt][2 * h + 1] + b1;
                if (ACT) {
                    v0 = (v0 > 0.f) ? (v0 + 1.f) : __expf(v0);
                    v1 = (v1 > 0.f) ? (v1 + 1.f) : __expf(v1);
                }
                *(float2*)(C + (size_t)row * N + col) = make_float2(v0, v1);
            }
        }
    }
}

// ---------------- zero the kv / ksum accumulators ---------------------------
__global__ void zero_kv_kernel()
{
    const int i = blockIdx.x * blockDim.x + threadIdx.x;
    if (i < NBATCH * NHEAD * HDIM * HDIM) g_kv[i] = 0.f;
    if (i < NBATCH * NHEAD * HDIM)        g_ksum[i] = 0.f;
}

// ---------------- kv = kf^T @ v per (b,h), split-K over sequence ------------
__global__ __launch_bounds__(256)
void kv_kernel()
{
    const int bh = blockIdx.x;
    const int split = blockIdx.y;
    const int b = bh >> 4, h = bh & 15;
    const int j0 = b * SEQ + split * 256;

    const float* Kp = g_k + (size_t)j0 * D_MODEL + h * HDIM;
    const float* Vp = g_v + (size_t)j0 * D_MODEL + h * HDIM;

    __shared__ __align__(16) float ks[8][64];
    __shared__ __align__(16) float vs[8][64];

    const int tid = threadIdx.x;
    const int eg = tid & 15, dg = tid >> 4;
    const int e0 = eg * 4, d0 = dg * 4;

    float acc[4][4];
#pragma unroll
    for (int i = 0; i < 4; ++i)
#pragma unroll
        for (int j = 0; j < 4; ++j) acc[i][j] = 0.f;
    float sacc[4] = {0.f, 0.f, 0.f, 0.f};

    for (int it = 0; it < 32; ++it) {
        const int rbase = it * 8;
        if (tid < 128) {
            const int r = tid >> 4, c = (tid & 15) * 4;
            *(float4*)&ks[r][c] = *(const float4*)(Kp + (size_t)(rbase + r) * D_MODEL + c);
        } else {
            const int t = tid - 128;
            const int r = t >> 4, c = (t & 15) * 4;
            *(float4*)&vs[r][c] = *(const float4*)(Vp + (size_t)(rbase + r) * D_MODEL + c);
        }
        __syncthreads();
#pragma unroll
        for (int r = 0; r < 8; ++r) {
            float4 kd4 = *(const float4*)&ks[r][d0];
            float4 ve4 = *(const float4*)&vs[r][e0];
            float kd[4] = {kd4.x, kd4.y, kd4.z, kd4.w};
            float ve[4] = {ve4.x, ve4.y, ve4.z, ve4.w};
#pragma unroll
            for (int i = 0; i < 4; ++i)
#pragma unroll
                for (int j = 0; j < 4; ++j)
                    acc[i][j] = fmaf(kd[i], ve[j], acc[i][j]);
            if (eg == 0) {
#pragma unroll
                for (int i = 0; i < 4; ++i) sacc[i] += kd[i];
            }
        }
        __syncthreads();
    }

    float* kvp = g_kv + (size_t)bh * HDIM * HDIM;
#pragma unroll
    for (int i = 0; i < 4; ++i)
#pragma unroll
        for (int j = 0; j < 4; ++j)
            atomicAdd(&kvp[(d0 + i) * HDIM + e0 + j], acc[i][j]);
    if (eg == 0) {
#pragma unroll
        for (int i = 0; i < 4; ++i)
            atomicAdd(&g_ksum[bh * HDIM + d0 + i], sacc[i]);
    }
}

// ---------------- attended = (qf @ kv) / max(qf . ksum, eps) ----------------
__global__ __launch_bounds__(256)
void attend_kernel()
{
    const int tile = blockIdx.x;
    const int bh = blockIdx.y;
    const int b = bh >> 4, h = bh & 15;
    const int row0 = b * SEQ + tile * 64;

    __shared__ __align__(16) float kvs[64][64];
    __shared__ __align__(16) float qs[64][64];
    __shared__ float ksum_s[64];

    const int tid = threadIdx.x;

    const float* kvp = g_kv + (size_t)bh * HDIM * HDIM;
    for (int i = tid; i < 1024; i += 256)
        ((float4*)kvs)[i] = ((const float4*)kvp)[i];
    if (tid < 64) ksum_s[tid] = g_ksum[bh * HDIM + tid];

    const float* Qp = g_q + (size_t)row0 * D_MODEL + h * HDIM;
    for (int i = tid; i < 1024; i += 256) {
        const int r = i >> 4, c = (i & 15) * 4;
        *(float4*)&qs[r][c] = *(const float4*)(Qp + (size_t)r * D_MODEL + c);
    }
    __syncthreads();

    const int cg = tid & 15, rg = tid >> 4;
    const int c0 = cg * 4, r0 = rg * 4;

    float num[4][4];
#pragma unroll
    for (int i = 0; i < 4; ++i)
#pragma unroll
        for (int j = 0; j < 4; ++j) num[i][j] = 0.f;
    float den[4] = {0.f, 0.f, 0.f, 0.f};

    for (int d = 0; d < 64; ++d) {
        float qv[4];
#pragma unroll
        for (int i = 0; i < 4; ++i) qv[i] = qs[r0 + i][d];
        float4 kv4 = *(const float4*)&kvs[d][c0];
        float kva[4] = {kv4.x, kv4.y, kv4.z, kv4.w};
        const float kd = ksum_s[d];
#pragma unroll
        for (int i = 0; i < 4; ++i) {
#pragma unroll
            for (int j = 0; j < 4; ++j)
                num[i][j] = fmaf(qv[i], kva[j], num[i][j]);
            den[i] = fmaf(qv[i], kd, den[i]);
        }
    }

    float* Op = g_att + (size_t)row0 * D_MODEL + h * HDIM;
#pragma unroll
    for (int i = 0; i < 4; ++i) {
        const float inv = 1.f / fmaxf(den[i], EPS_V);
        *(float4*)(Op + (size_t)(r0 + i) * D_MODEL + c0) =
            make_float4(num[i][0] * inv, num[i][1] * inv,
                        num[i][2] * inv, num[i][3] * inv);
    }
}

// ---------------- launch ----------------------------------------------------
extern "C" void kernel_launch(void* const* d_in, const int* in_sizes, int n_in,
                              void* d_out, int out_size)
{
    const float* x  = (const float*)d_in[0];
    const float* wq = (const float*)d_in[1];
    const float* bq = (const float*)d_in[2];
    const float* wk = (const float*)d_in[3];
    const float* bk = (const float*)d_in[4];
    const float* wv = (const float*)d_in[5];
    const float* bv = (const float*)d_in[6];
    const float* wo = (const float*)d_in[7];
    const float* bo = (const float*)d_in[8];
    float* out = (float*)d_out;

    const int M = in_sizes[0] / D_MODEL;   // 4096

    float *qp, *kp, *vp, *ap;
    cudaGetSymbolAddress((void**)&qp, g_q);
    cudaGetSymbolAddress((void**)&kp, g_k);
    cudaGetSymbolAddress((void**)&vp, g_v);
    cudaGetSymbolAddress((void**)&ap, g_att);

    cudaFuncSetAttribute(gemm_mma<0>, cudaFuncAttributeMaxDynamicSharedMemorySize, GEMM_SMEM);
    cudaFuncSetAttribute(gemm_mma<1>, cudaFuncAttributeMaxDynamicSharedMemorySize, GEMM_SMEM);

    dim3 gridP(D_MODEL / BN, M / BM);  // (8, 32)

    gemm_mma<1><<<gridP, 256, GEMM_SMEM>>>(x, wq, bq, qp, M, D_MODEL, D_MODEL);
    gemm_mma<1><<<gridP, 256, GEMM_SMEM>>>(x, wk, bk, kp, M, D_MODEL, D_MODEL);
    gemm_mma<0><<<gridP, 256, GEMM_SMEM>>>(x, wv, bv, vp, M, D_MODEL, D_MODEL);

    zero_kv_kernel<<<(NBATCH * NHEAD * HDIM * HDIM + 255) / 256, 256>>>();
    kv_kernel<<<dim3(NBATCH * NHEAD, 8), 256>>>();
    attend_kernel<<<dim3(SEQ / 64, NBATCH * NHEAD), 256>>>();

    gemm_mma<0><<<gridP, 256, GEMM_SMEM>>>(ap, wo, bo, out, M, D_MODEL, D_MODEL);
}

// round 4
// speedup vs baseline: 2.7636x; 1.0990x over previous
#include <cuda_runtime.h>
#include <cuda_bf16.h>
#include <cstdint>
#include <math.h>

#define D_MODEL 1024
#define NHEAD 16
#define HDIM 64
#define SEQ 2048
#define NBATCH 2
#define NROWS (NBATCH * SEQ)          // 4096
#define EPS_V 1e-6f

typedef uint16_t u16;
typedef uint32_t u32;

// ---------------- scratch (device globals; no allocation allowed) -----------
__device__ float g_q[NROWS * D_MODEL];
__device__ float g_k[NROWS * D_MODEL];
__device__ float g_v[NROWS * D_MODEL];
__device__ float g_kv[NBATCH * NHEAD * HDIM * HDIM];
__device__ float g_ksum[NBATCH * NHEAD * HDIM];

// bf16 split planes
__device__ __align__(16) u16 g_xh[NROWS * D_MODEL];
__device__ __align__(16) u16 g_xl[NROWS * D_MODEL];
__device__ __align__(16) u16 g_oh[NROWS * D_MODEL];   // attend output hi
__device__ __align__(16) u16 g_ol[NROWS * D_MODEL];   // attend output lo
__device__ __align__(16) u16 g_wh[4][D_MODEL * D_MODEL];
__device__ __align__(16) u16 g_wl[4][D_MODEL * D_MODEL];

__device__ __forceinline__ u32 smem_u32(const void* p) {
    u32 a;
    asm("{ .reg .u64 t; cvta.to.shared.u64 t, %1; cvt.u32.u64 %0, t; }"
        : "=r"(a) : "l"(p));
    return a;
}

__device__ __forceinline__ void ldsm4(u32* r, u32 addr) {
    asm volatile("ldmatrix.sync.aligned.m8n8.x4.shared.b16 {%0,%1,%2,%3}, [%4];"
                 : "=r"(r[0]), "=r"(r[1]), "=r"(r[2]), "=r"(r[3]) : "r"(addr));
}

__device__ __forceinline__ void mma16816(float* c, const u32* a, u32 b0, u32 b1) {
    asm volatile(
        "mma.sync.aligned.m16n8k16.row.col.f32.bf16.bf16.f32 "
        "{%0,%1,%2,%3}, {%4,%5,%6,%7}, {%8,%9}, {%0,%1,%2,%3};"
        : "+f"(c[0]), "+f"(c[1]), "+f"(c[2]), "+f"(c[3])
        : "r"(a[0]), "r"(a[1]), "r"(a[2]), "r"(a[3]), "r"(b0), "r"(b1));
}

#define CP16(dst, src) \
    asm volatile("cp.async.cg.shared.global [%0], [%1], 16;" :: "r"(dst), "l"(src))
#define CP_COMMIT() asm volatile("cp.async.commit_group;" ::: "memory")
#define CP_WAIT0()  asm volatile("cp.async.wait_group 0;" ::: "memory")
#define CP_WAIT1()  asm volatile("cp.async.wait_group 1;" ::: "memory")

// helper: split one float4 into packed hi-pair / lo-pair bf16x2 words
__device__ __forceinline__ void split4(float4 f, u32& h0, u32& h1, u32& l0, u32& l1) {
    u32 bx = __float_as_uint(f.x), by = __float_as_uint(f.y);
    u32 bz = __float_as_uint(f.z), bw = __float_as_uint(f.w);
    h0 = __byte_perm(bx, by, 0x7632);
    h1 = __byte_perm(bz, bw, 0x7632);
    float lx = f.x - __uint_as_float(bx & 0xFFFF0000u);
    float ly = f.y - __uint_as_float(by & 0xFFFF0000u);
    float lz = f.z - __uint_as_float(bz & 0xFFFF0000u);
    float lw = f.w - __uint_as_float(bw & 0xFFFF0000u);
    asm("cvt.rn.bf16x2.f32 %0, %1, %2;" : "=r"(l0) : "f"(ly), "f"(lx));
    asm("cvt.rn.bf16x2.f32 %0, %1, %2;" : "=r"(l1) : "f"(lw), "f"(lz));
}

// ---------------- conversion passes -----------------------------------------
__global__ __launch_bounds__(256) void split_x_kernel(const float* __restrict__ src)
{
    const int i = blockIdx.x * 256 + threadIdx.x;           // float4 index
    float4 f = ((const float4*)src)[i];
    u32 h0, h1, l0, l1;
    split4(f, h0, h1, l0, l1);
    ((uint2*)g_xh)[i] = make_uint2(h0, h1);
    ((uint2*)g_xl)[i] = make_uint2(l0, l1);
}

__global__ __launch_bounds__(256) void split_w_kernel(
    const float* __restrict__ w0, const float* __restrict__ w1,
    const float* __restrict__ w2, const float* __restrict__ w3)
{
    const int m = blockIdx.y;
    const float* src = (m == 0) ? w0 : (m == 1) ? w1 : (m == 2) ? w2 : w3;
    const int i = blockIdx.x * 256 + threadIdx.x;
    float4 f = ((const float4*)src)[i];
    u32 h0, h1, l0, l1;
    split4(f, h0, h1, l0, l1);
    ((uint2*)g_wh[m])[i] = make_uint2(h0, h1);
    ((uint2*)g_wl[m])[i] = make_uint2(l0, l1);
}

// ======================= bf16 3-term split GEMM (cp.async + mma.sync) ========
// C[M,N] = A[M,K] @ W[N,K]^T + bias.  blockIdx.z selects weight/output set.
// BM=BN=128, BK=64 bf16. 8 warps (2 M x 4 N), warp tile 64x32.
// smem: 2 buffers x 4 planes (A_hi, A_lo, W_hi, W_lo) x 16KB = 128KB.
#define BM 128
#define BN 128
#define PLANE_B 16384
#define BUF_B (4 * PLANE_B)
#define GEMM_SMEM (2 * BUF_B)    // 131072

__global__ __launch_bounds__(256, 1)
void gemm3(const u16* __restrict__ Ah, const u16* __restrict__ Al,
           const u16* __restrict__ W0h, const u16* __restrict__ W0l,
           const u16* __restrict__ W1h, const u16* __restrict__ W1l,
           const u16* __restrict__ W2h, const u16* __restrict__ W2l,
           const float* __restrict__ b0, const float* __restrict__ b1,
           const float* __restrict__ b2,
           float* __restrict__ C0, float* __restrict__ C1, float* __restrict__ C2,
           int M, int N, int K, int actmask)
{
    extern __shared__ __align__(1024) char smem[];
    const u32 sb = smem_u32(smem);

    const int tid = threadIdx.x;
    const int lane = tid & 31, wid = tid >> 5;
    const int wm = wid >> 2, wn = wid & 3;
    const int bm = blockIdx.y * BM, bn = blockIdx.x * BN;
    const int z = blockIdx.z;

    const u16* Wh = (z == 0) ? W0h : (z == 1) ? W1h : W2h;
    const u16* Wl = (z == 0) ? W0l : (z == 1) ? W1l : W2l;
    const float* bias = (z == 0) ? b0 : (z == 1) ? b1 : b2;
    float* C = (z == 0) ? C0 : (z == 1) ? C1 : C2;
    const int act = (actmask >> z) & 1;

    // ---- cp.async loader indexing: thread -> (row, 16B col chunk) ----
    // per plane: 128 rows x 8 chunks = 1024 chunks; 4 iters x 256 threads
    const int NCH = K / 64;

    // ---- ldmatrix addressing (same layout as R3) ----
    const int arow_l = (lane & 15);
    const u32 akb = (u32)((lane >> 4) * 16);
    const int brow_l = (lane & 7) + ((lane >> 4) << 3);
    const u32 bkb = (u32)(((lane >> 3) & 1) * 16);

    u32 abase[4], axor[4];
#pragma unroll
    for (int mt = 0; mt < 4; ++mt) {
        const int r = wm * 64 + mt * 16 + arow_l;
        abase[mt] = (u32)(r * 128);
        axor[mt] = (u32)((r & 7) << 4);
    }
    u32 bbase[2], bxor[2];
#pragma unroll
    for (int p = 0; p < 2; ++p) {
        const int r = wn * 32 + p * 16 + brow_l;
        bbase[p] = (u32)(r * 128);
        bxor[p] = (u32)((r & 7) << 4);
    }

    float acc[4][4][4];
#pragma unroll
    for (int i = 0; i < 4; ++i)
#pragma unroll
        for (int j = 0; j < 4; ++j)
#pragma unroll
            for (int d = 0; d < 4; ++d) acc[i][j][d] = 0.f;

    // loader lambda
    auto load_chunk = [&](int c, int buf) {
        const u32 bufb = sb + buf * BUF_B;
        const size_t kc = (size_t)c * 64;
#pragma unroll
        for (int i = 0; i < 4; ++i) {
            const int idx = i * 256 + tid;
            const int r = idx >> 3, c16 = idx & 7;
            const u32 dsto = (u32)(r * 128 + ((c16 * 16) ^ ((r & 7) * 16)));
            const size_t asrc = (size_t)(bm + r) * K + kc + c16 * 8;
            const size_t wsrc = (size_t)(bn + r) * K + kc + c16 * 8;
            CP16(bufb + dsto, Ah + asrc);
            CP16(bufb + PLANE_B + dsto, Al + asrc);
            CP16(bufb + 2 * PLANE_B + dsto, Wh + wsrc);
            CP16(bufb + 3 * PLANE_B + dsto, Wl + wsrc);
        }
        CP_COMMIT();
    };

    load_chunk(0, 0);

    for (int c = 0; c < NCH; ++c) {
        if (c + 1 < NCH) {
            load_chunk(c + 1, (c + 1) & 1);
            CP_WAIT1();
        } else {
            CP_WAIT0();
        }
        __syncthreads();

        const u32 bufb = sb + (c & 1) * BUF_B;
        const u32 AHb = bufb, ALb = bufb + PLANE_B;
        const u32 WHb = bufb + 2 * PLANE_B, WLb = bufb + 3 * PLANE_B;

#pragma unroll
        for (int ks = 0; ks < 4; ++ks) {
            u32 ah[4][4], al[4][4], bh[2][4], bl[2][4];
#pragma unroll
            for (int mt = 0; mt < 4; ++mt) {
                const u32 t = ((u32)(ks * 32) + akb) ^ axor[mt];
                ldsm4(ah[mt], AHb + abase[mt] + t);
                ldsm4(al[mt], ALb + abase[mt] + t);
            }
#pragma unroll
            for (int p = 0; p < 2; ++p) {
                const u32 t = ((u32)(ks * 32) + bkb) ^ bxor[p];
                ldsm4(bh[p], WHb + bbase[p] + t);
                ldsm4(bl[p], WLb + bbase[p] + t);
            }
#pragma unroll
            for (int mt = 0; mt < 4; ++mt)
#pragma unroll
                for (int nt = 0; nt < 4; ++nt) {
                    const int p = nt >> 1, q = (nt & 1) * 2;
                    mma16816(acc[mt][nt], ah[mt], bh[p][q], bh[p][q + 1]);
                    mma16816(acc[mt][nt], ah[mt], bl[p][q], bl[p][q + 1]);
                    mma16816(acc[mt][nt], al[mt], bh[p][q], bh[p][q + 1]);
                }
        }
        __syncthreads();
    }

    // ---- epilogue ----
    const int erow = bm + wm * 64 + (lane >> 2);
    const int ecol0 = bn + wn * 32 + (lane & 3) * 2;
#pragma unroll
    for (int nt = 0; nt < 4; ++nt) {
        const int col = ecol0 + nt * 8;
        const float bb0 = bias[col], bb1 = bias[col + 1];
#pragma unroll
        for (int mt = 0; mt < 4; ++mt) {
#pragma unroll
            for (int h = 0; h < 2; ++h) {
                const int row = erow + mt * 16 + h * 8;
                float v0 = acc[mt][nt][2 * h] + bb0;
                float v1 = acc[mt][nt][2 * h + 1] + bb1;
                if (act) {
                    v0 = (v0 > 0.f) ? (v0 + 1.f) : __expf(v0);
                    v1 = (v1 > 0.f) ? (v1 + 1.f) : __expf(v1);
                }
                *(float2*)(C + (size_t)row * N + col) = make_float2(v0, v1);
            }
        }
    }
}

// ---------------- zero the kv / ksum accumulators ---------------------------
__global__ void zero_kv_kernel()
{
    const int i = blockIdx.x * blockDim.x + threadIdx.x;
    if (i < NBATCH * NHEAD * HDIM * HDIM) g_kv[i] = 0.f;
    if (i < NBATCH * NHEAD * HDIM)        g_ksum[i] = 0.f;
}

// ---------------- kv = kf^T @ v per (b,h), split-K over sequence ------------
__global__ __launch_bounds__(256)
void kv_kernel()
{
    const int bh = blockIdx.x;
    const int split = blockIdx.y;
    const int b = bh >> 4, h = bh & 15;
    const int j0 = b * SEQ + split * 256;

    const float* Kp = g_k + (size_t)j0 * D_MODEL + h * HDIM;
    const float* Vp = g_v + (size_t)j0 * D_MODEL + h * HDIM;

    __shared__ __align__(16) float ks[8][64];
    __shared__ __align__(16) float vs[8][64];

    const int tid = threadIdx.x;
    const int eg = tid & 15, dg = tid >> 4;
    const int e0 = eg * 4, d0 = dg * 4;

    float acc[4][4];
#pragma unroll
    for (int i = 0; i < 4; ++i)
#pragma unroll
        for (int j = 0; j < 4; ++j) acc[i][j] = 0.f;
    float sacc[4] = {0.f, 0.f, 0.f, 0.f};

    for (int it = 0; it < 32; ++it) {
        const int rbase = it * 8;
        if (tid < 128) {
            const int r = tid >> 4, c = (tid & 15) * 4;
            *(float4*)&ks[r][c] = *(const float4*)(Kp + (size_t)(rbase + r) * D_MODEL + c);
        } else {
            const int t = tid - 128;
            const int r = t >> 4, c = (t & 15) * 4;
            *(float4*)&vs[r][c] = *(const float4*)(Vp + (size_t)(rbase + r) * D_MODEL + c);
        }
        __syncthreads();
#pragma unroll
        for (int r = 0; r < 8; ++r) {
            float4 kd4 = *(const float4*)&ks[r][d0];
            float4 ve4 = *(const float4*)&vs[r][e0];
            float kd[4] = {kd4.x, kd4.y, kd4.z, kd4.w};
            float ve[4] = {ve4.x, ve4.y, ve4.z, ve4.w};
#pragma unroll
            for (int i = 0; i < 4; ++i)
#pragma unroll
                for (int j = 0; j < 4; ++j)
                    acc[i][j] = fmaf(kd[i], ve[j], acc[i][j]);
            if (eg == 0) {
#pragma unroll
                for (int i = 0; i < 4; ++i) sacc[i] += kd[i];
            }
        }
        __syncthreads();
    }

    float* kvp = g_kv + (size_t)bh * HDIM * HDIM;
#pragma unroll
    for (int i = 0; i < 4; ++i)
#pragma unroll
        for (int j = 0; j < 4; ++j)
            atomicAdd(&kvp[(d0 + i) * HDIM + e0 + j], acc[i][j]);
    if (eg == 0) {
#pragma unroll
        for (int i = 0; i < 4; ++i)
            atomicAdd(&g_ksum[bh * HDIM + d0 + i], sacc[i]);
    }
}

// ---------------- attended = (qf @ kv) / max(qf . ksum, eps) -----------------
// writes bf16 hi/lo planes directly (feeds the O-GEMM)
__global__ __launch_bounds__(256)
void attend_kernel()
{
    const int tile = blockIdx.x;
    const int bh = blockIdx.y;
    const int b = bh >> 4, h = bh & 15;
    const int row0 = b * SEQ + tile * 64;

    __shared__ __align__(16) float kvs[64][64];
    __shared__ __align__(16) float qs[64][64];
    __shared__ float ksum_s[64];

    const int tid = threadIdx.x;

    const float* kvp = g_kv + (size_t)bh * HDIM * HDIM;
    for (int i = tid; i < 1024; i += 256)
        ((float4*)kvs)[i] = ((const float4*)kvp)[i];
    if (tid < 64) ksum_s[tid] = g_ksum[bh * HDIM + tid];

    const float* Qp = g_q + (size_t)row0 * D_MODEL + h * HDIM;
    for (int i = tid; i < 1024; i += 256) {
        const int r = i >> 4, c = (i & 15) * 4;
        *(float4*)&qs[r][c] = *(const float4*)(Qp + (size_t)r * D_MODEL + c);
    }
    __syncthreads();

    const int cg = tid & 15, rg = tid >> 4;
    const int c0 = cg * 4, r0 = rg * 4;

    float num[4][4];
#pragma unroll
    for (int i = 0; i < 4; ++i)
#pragma unroll
        for (int j = 0; j < 4; ++j) num[i][j] = 0.f;
    float den[4] = {0.f, 0.f, 0.f, 0.f};

    for (int d = 0; d < 64; ++d) {
        float qv[4];
#pragma unroll
        for (int i = 0; i < 4; ++i) qv[i] = qs[r0 + i][d];
        float4 kv4 = *(const float4*)&kvs[d][c0];
        float kva[4] = {kv4.x, kv4.y, kv4.z, kv4.w};
        const float kd = ksum_s[d];
#pragma unroll
        for (int i = 0; i < 4; ++i) {
#pragma unroll
            for (int j = 0; j < 4; ++j)
                num[i][j] = fmaf(qv[i], kva[j], num[i][j]);
            den[i] = fmaf(qv[i], kd, den[i]);
        }
    }

#pragma unroll
    for (int i = 0; i < 4; ++i) {
        const float inv = 1.f / fmaxf(den[i], EPS_V);
        float4 res = make_float4(num[i][0] * inv, num[i][1] * inv,
                                 num[i][2] * inv, num[i][3] * inv);
        u32 h0, h1, l0, l1;
        split4(res, h0, h1, l0, l1);
        const size_t e4 = ((size_t)(row0 + r0 + i) * D_MODEL + h * HDIM + c0) >> 2;
        ((uint2*)g_oh)[e4] = make_uint2(h0, h1);
        ((uint2*)g_ol)[e4] = make_uint2(l0, l1);
    }
}

// ---------------- launch -----------------------------------------------------
extern "C" void kernel_launch(void* const* d_in, const int* in_sizes, int n_in,
                              void* d_out, int out_size)
{
    const float* x  = (const float*)d_in[0];
    const float* wq = (const float*)d_in[1];
    const float* bq = (const float*)d_in[2];
    const float* wk = (const float*)d_in[3];
    const float* bk = (const float*)d_in[4];
    const float* wv = (const float*)d_in[5];
    const float* bv = (const float*)d_in[6];
    const float* wo = (const float*)d_in[7];
    const float* bo = (const float*)d_in[8];
    float* out = (float*)d_out;

    const int M = in_sizes[0] / D_MODEL;   // 4096

    float *qp, *kp, *vp;
    u16 *xh, *xl, *oh, *ol, *wh, *wl;
    cudaGetSymbolAddress((void**)&qp, g_q);
    cudaGetSymbolAddress((void**)&kp, g_k);
    cudaGetSymbolAddress((void**)&vp, g_v);
    cudaGetSymbolAddress((void**)&xh, g_xh);
    cudaGetSymbolAddress((void**)&xl, g_xl);
    cudaGetSymbolAddress((void**)&oh, g_oh);
    cudaGetSymbolAddress((void**)&ol, g_ol);
    cudaGetSymbolAddress((void**)&wh, g_wh);
    cudaGetSymbolAddress((void**)&wl, g_wl);

    const u16* whp[4] = {wh, wh + (size_t)D_MODEL * D_MODEL,
                         wh + 2 * (size_t)D_MODEL * D_MODEL,
                         wh + 3 * (size_t)D_MODEL * D_MODEL};
    const u16* wlp[4] = {wl, wl + (size_t)D_MODEL * D_MODEL,
                         wl + 2 * (size_t)D_MODEL * D_MODEL,
                         wl + 3 * (size_t)D_MODEL * D_MODEL};

    cudaFuncSetAttribute(gemm3, cudaFuncAttributeMaxDynamicSharedMemorySize, GEMM_SMEM);

    // conversion passes
    split_x_kernel<<<(M * D_MODEL / 4) / 256, 256>>>(x);
    split_w_kernel<<<dim3((D_MODEL * D_MODEL / 4) / 256, 4), 256>>>(wq, wk, wv, wo);

    // fused Q/K/V projection GEMMs (act on q,k only)
    gemm3<<<dim3(D_MODEL / BN, M / BM, 3), 256, GEMM_SMEM>>>(
        xh, xl,
        whp[0], wlp[0], whp[1], wlp[1], whp[2], wlp[2],
        bq, bk, bv, qp, kp, vp,
        M, D_MODEL, D_MODEL, 0b011);

    zero_kv_kernel<<<(NBATCH * NHEAD * HDIM * HDIM + 255) / 256, 256>>>();
    kv_kernel<<<dim3(NBATCH * NHEAD, 8), 256>>>();
    attend_kernel<<<dim3(SEQ / 64, NBATCH * NHEAD), 256>>>();

    // output projection
    gemm3<<<dim3(D_MODEL / BN, M / BM, 1), 256, GEMM_SMEM>>>(
        oh, ol,
        whp[3], wlp[3], whp[3], wlp[3], whp[3], wlp[3],
        bo, bo, bo, out, out, out,
        M, D_MODEL, D_MODEL, 0);
}

// round 5
// speedup vs baseline: 2.7639x; 1.0001x over previous
#include <cuda_runtime.h>
#include <cuda_bf16.h>
#include <cstdint>
#include <math.h>

#define D_MODEL 1024
#define NHEAD 16
#define HDIM 64
#define SEQ 2048
#define NBATCH 2
#define NROWS (NBATCH * SEQ)          // 4096
#define EPS_V 1e-6f

typedef uint16_t u16;
typedef uint32_t u32;

// ---------------- scratch (device globals; no allocation allowed) -----------
__device__ float g_q[NROWS * D_MODEL];
__device__ float g_k[NROWS * D_MODEL];
__device__ float g_v[NROWS * D_MODEL];
__device__ float g_kv[NBATCH * NHEAD * HDIM * HDIM];
__device__ float g_ksum[NBATCH * NHEAD * HDIM];

// bf16 split planes
__device__ __align__(16) u16 g_xh[NROWS * D_MODEL];
__device__ __align__(16) u16 g_xl[NROWS * D_MODEL];
__device__ __align__(16) u16 g_oh[NROWS * D_MODEL];
__device__ __align__(16) u16 g_ol[NROWS * D_MODEL];
// packed weights: rows [0,1024)=wq, [1024,2048)=wk, [2048,3072)=wv, [3072,4096)=wo
__device__ __align__(16) u16 g_wh[4 * D_MODEL * D_MODEL];
__device__ __align__(16) u16 g_wl[4 * D_MODEL * D_MODEL];

__device__ __forceinline__ u32 smem_u32(const void* p) {
    u32 a;
    asm("{ .reg .u64 t; cvta.to.shared.u64 t, %1; cvt.u32.u64 %0, t; }"
        : "=r"(a) : "l"(p));
    return a;
}

__device__ __forceinline__ void ldsm4(u32* r, u32 addr) {
    asm volatile("ldmatrix.sync.aligned.m8n8.x4.shared.b16 {%0,%1,%2,%3}, [%4];"
                 : "=r"(r[0]), "=r"(r[1]), "=r"(r[2]), "=r"(r[3]) : "r"(addr));
}

__device__ __forceinline__ void mma16816(float* c, const u32* a, u32 b0, u32 b1) {
    asm volatile(
        "mma.sync.aligned.m16n8k16.row.col.f32.bf16.bf16.f32 "
        "{%0,%1,%2,%3}, {%4,%5,%6,%7}, {%8,%9}, {%0,%1,%2,%3};"
        : "+f"(c[0]), "+f"(c[1]), "+f"(c[2]), "+f"(c[3])
        : "r"(a[0]), "r"(a[1]), "r"(a[2]), "r"(a[3]), "r"(b0), "r"(b1));
}

#define CP16(dst, src) \
    asm volatile("cp.async.cg.shared.global [%0], [%1], 16;" :: "r"(dst), "l"(src))
#define CP_COMMIT() asm volatile("cp.async.commit_group;" ::: "memory")
#define CP_WAIT0()  asm volatile("cp.async.wait_group 0;" ::: "memory")
#define CP_WAIT1()  asm volatile("cp.async.wait_group 1;" ::: "memory")

__device__ __forceinline__ void split4(float4 f, u32& h0, u32& h1, u32& l0, u32& l1) {
    u32 bx = __float_as_uint(f.x), by = __float_as_uint(f.y);
    u32 bz = __float_as_uint(f.z), bw = __float_as_uint(f.w);
    h0 = __byte_perm(bx, by, 0x7632);
    h1 = __byte_perm(bz, bw, 0x7632);
    float lx = f.x - __uint_as_float(bx & 0xFFFF0000u);
    float ly = f.y - __uint_as_float(by & 0xFFFF0000u);
    float lz = f.z - __uint_as_float(bz & 0xFFFF0000u);
    float lw = f.w - __uint_as_float(bw & 0xFFFF0000u);
    asm("cvt.rn.bf16x2.f32 %0, %1, %2;" : "=r"(l0) : "f"(ly), "f"(lx));
    asm("cvt.rn.bf16x2.f32 %0, %1, %2;" : "=r"(l1) : "f"(lw), "f"(lz));
}

// ---------------- conversion passes -----------------------------------------
__global__ __launch_bounds__(256) void split_x_kernel(const float* __restrict__ src)
{
    const int i = blockIdx.x * 256 + threadIdx.x;
    float4 f = ((const float4*)src)[i];
    u32 h0, h1, l0, l1;
    split4(f, h0, h1, l0, l1);
    ((uint2*)g_xh)[i] = make_uint2(h0, h1);
    ((uint2*)g_xl)[i] = make_uint2(l0, l1);
}

__global__ __launch_bounds__(256) void split_w_kernel(
    const float* __restrict__ w0, const float* __restrict__ w1,
    const float* __restrict__ w2, const float* __restrict__ w3)
{
    const int m = blockIdx.y;
    const float* src = (m == 0) ? w0 : (m == 1) ? w1 : (m == 2) ? w2 : w3;
    const size_t i = blockIdx.x * 256 + threadIdx.x;
    float4 f = ((const float4*)src)[i];
    u32 h0, h1, l0, l1;
    split4(f, h0, h1, l0, l1);
    const size_t o = (size_t)m * (D_MODEL * D_MODEL / 4) + i;
    ((uint2*)g_wh)[o] = make_uint2(h0, h1);
    ((uint2*)g_wl)[o] = make_uint2(l0, l1);
}

// ======================= bf16 3-term split GEMM ==============================
// C_seg[M,1024] = A[M,K] @ Wseg[1024,K]^T + b_seg, seg = blockIdx.x>>3.
// BM=BN=128. 8 warps (2M x 4N), warp tile 64x32. 3-stage cp.async pipeline.
#define BM 128
#define BN 128
#define PLANE_B 16384
#define STAGE_B (4 * PLANE_B)          // 65536
#define GEMM_SMEM (3 * STAGE_B)        // 196608

__global__ __launch_bounds__(256, 1)
void gemm3s(const u16* __restrict__ Ah, const u16* __restrict__ Al,
            const u16* __restrict__ Wh, const u16* __restrict__ Wl,
            const float* __restrict__ b0, const float* __restrict__ b1,
            const float* __restrict__ b2,
            float* __restrict__ C0, float* __restrict__ C1, float* __restrict__ C2,
            int M, int K, int actmask)
{
    extern __shared__ __align__(1024) char smem[];
    const u32 sb = smem_u32(smem);

    const int tid = threadIdx.x;
    const int lane = tid & 31, wid = tid >> 5;
    const int wm = wid >> 2, wn = wid & 3;
    const int bm = blockIdx.y * BM;
    const int bng = blockIdx.x * BN;          // global col in packed weight
    const int seg = blockIdx.x >> 3;          // 1024/BN = 8 tiles per segment
    const int bns = bng & 1023;               // col within segment

    const float* bias = (seg == 0) ? b0 : (seg == 1) ? b1 : b2;
    float* C = (seg == 0) ? C0 : (seg == 1) ? C1 : C2;
    const int act = (actmask >> seg) & 1;

    const int NCH = K / 64;

    // ---- ldmatrix addressing ----
    const int arow_l = (lane & 15);
    const u32 akb = (u32)((lane >> 4) * 16);
    const int brow_l = (lane & 7) + ((lane >> 4) << 3);
    const u32 bkb = (u32)(((lane >> 3) & 1) * 16);

    u32 abase[4], axor[4];
#pragma unroll
    for (int mt = 0; mt < 4; ++mt) {
        const int r = wm * 64 + mt * 16 + arow_l;
        abase[mt] = (u32)(r * 128);
        axor[mt] = (u32)((r & 7) << 4);
    }
    u32 bbase[2], bxor[2];
#pragma unroll
    for (int p = 0; p < 2; ++p) {
        const int r = wn * 32 + p * 16 + brow_l;
        bbase[p] = (u32)(r * 128);
        bxor[p] = (u32)((r & 7) << 4);
    }

    float acc[4][4][4];
#pragma unroll
    for (int i = 0; i < 4; ++i)
#pragma unroll
        for (int j = 0; j < 4; ++j)
#pragma unroll
            for (int d = 0; d < 4; ++d) acc[i][j][d] = 0.f;

    auto load_chunk = [&](int c, int stage) {
        const u32 bufb = sb + stage * STAGE_B;
        const size_t kc = (size_t)c * 64;
#pragma unroll
        for (int i = 0; i < 4; ++i) {
            const int idx = i * 256 + tid;
            const int r = idx >> 3, c16 = idx & 7;
            const u32 dsto = (u32)(r * 128 + ((c16 * 16) ^ ((r & 7) * 16)));
            const size_t asrc = (size_t)(bm + r) * K + kc + c16 * 8;
            const size_t wsrc = (size_t)(bng + r) * K + kc + c16 * 8;
            CP16(bufb + dsto, Ah + asrc);
            CP16(bufb + PLANE_B + dsto, Al + asrc);
            CP16(bufb + 2 * PLANE_B + dsto, Wh + wsrc);
            CP16(bufb + 3 * PLANE_B + dsto, Wl + wsrc);
        }
        CP_COMMIT();
    };

    load_chunk(0, 0);
    load_chunk(1, 1);

    int stage = 0;
    for (int c = 0; c < NCH; ++c) {
        if (c == NCH - 1) { CP_WAIT0(); } else { CP_WAIT1(); }
        __syncthreads();
        if (c + 2 < NCH) {
            int s2 = stage + 2; if (s2 >= 3) s2 -= 3;
            load_chunk(c + 2, s2);
        }

        const u32 bufb = sb + stage * STAGE_B;
        const u32 AHb = bufb, ALb = bufb + PLANE_B;
        const u32 WHb = bufb + 2 * PLANE_B, WLb = bufb + 3 * PLANE_B;

#pragma unroll
        for (int ks = 0; ks < 4; ++ks) {
            u32 ah[4][4], al[4][4], bh[2][4], bl[2][4];
#pragma unroll
            for (int mt = 0; mt < 4; ++mt) {
                const u32 t = ((u32)(ks * 32) + akb) ^ axor[mt];
                ldsm4(ah[mt], AHb + abase[mt] + t);
                ldsm4(al[mt], ALb + abase[mt] + t);
            }
#pragma unroll
            for (int p = 0; p < 2; ++p) {
                const u32 t = ((u32)(ks * 32) + bkb) ^ bxor[p];
                ldsm4(bh[p], WHb + bbase[p] + t);
                ldsm4(bl[p], WLb + bbase[p] + t);
            }
            // term-outer: 16 independent mmas between same-acc writes
#pragma unroll
            for (int mt = 0; mt < 4; ++mt)
#pragma unroll
                for (int nt = 0; nt < 4; ++nt) {
                    const int p = nt >> 1, q = (nt & 1) * 2;
                    mma16816(acc[mt][nt], ah[mt], bh[p][q], bh[p][q + 1]);
                }
#pragma unroll
            for (int mt = 0; mt < 4; ++mt)
#pragma unroll
                for (int nt = 0; nt < 4; ++nt) {
                    const int p = nt >> 1, q = (nt & 1) * 2;
                    mma16816(acc[mt][nt], ah[mt], bl[p][q], bl[p][q + 1]);
                }
#pragma unroll
            for (int mt = 0; mt < 4; ++mt)
#pragma unroll
                for (int nt = 0; nt < 4; ++nt) {
                    const int p = nt >> 1, q = (nt & 1) * 2;
                    mma16816(acc[mt][nt], al[mt], bh[p][q], bh[p][q + 1]);
                }
        }
        ++stage; if (stage == 3) stage = 0;
    }

    // ---- epilogue ----
    const int erow = bm + wm * 64 + (lane >> 2);
    const int ecol0 = bns + wn * 32 + (lane & 3) * 2;
#pragma unroll
    for (int nt = 0; nt < 4; ++nt) {
        const int col = ecol0 + nt * 8;
        const float bb0 = bias[col], bb1 = bias[col + 1];
#pragma unroll
        for (int mt = 0; mt < 4; ++mt) {
#pragma unroll
            for (int h = 0; h < 2; ++h) {
                const int row = erow + mt * 16 + h * 8;
                float v0 = acc[mt][nt][2 * h] + bb0;
                float v1 = acc[mt][nt][2 * h + 1] + bb1;
                if (act) {
                    v0 = (v0 > 0.f) ? (v0 + 1.f) : __expf(v0);
                    v1 = (v1 > 0.f) ? (v1 + 1.f) : __expf(v1);
                }
                *(float2*)(C + (size_t)row * D_MODEL + col) = make_float2(v0, v1);
            }
        }
    }
}

// ---------------- zero the kv / ksum accumulators ---------------------------
__global__ void zero_kv_kernel()
{
    const int i = blockIdx.x * blockDim.x + threadIdx.x;
    if (i < NBATCH * NHEAD * HDIM * HDIM) g_kv[i] = 0.f;
    if (i < NBATCH * NHEAD * HDIM)        g_ksum[i] = 0.f;
}

// ---------------- kv = kf^T @ v per (b,h), split-K over sequence ------------
__global__ __launch_bounds__(256)
void kv_kernel()
{
    const int bh = blockIdx.x;
    const int split = blockIdx.y;
    const int b = bh >> 4, h = bh & 15;
    const int j0 = b * SEQ + split * 256;

    const float* Kp = g_k + (size_t)j0 * D_MODEL + h * HDIM;
    const float* Vp = g_v + (size_t)j0 * D_MODEL + h * HDIM;

    __shared__ __align__(16) float ks[8][64];
    __shared__ __align__(16) float vs[8][64];

    const int tid = threadIdx.x;
    const int eg = tid & 15, dg = tid >> 4;
    const int e0 = eg * 4, d0 = dg * 4;

    float acc[4][4];
#pragma unroll
    for (int i = 0; i < 4; ++i)
#pragma unroll
        for (int j = 0; j < 4; ++j) acc[i][j] = 0.f;
    float sacc[4] = {0.f, 0.f, 0.f, 0.f};

    for (int it = 0; it < 32; ++it) {
        const int rbase = it * 8;
        if (tid < 128) {
            const int r = tid >> 4, c = (tid & 15) * 4;
            *(float4*)&ks[r][c] = *(const float4*)(Kp + (size_t)(rbase + r) * D_MODEL + c);
        } else {
            const int t = tid - 128;
            const int r = t >> 4, c = (t & 15) * 4;
            *(float4*)&vs[r][c] = *(const float4*)(Vp + (size_t)(rbase + r) * D_MODEL + c);
        }
        __syncthreads();
#pragma unroll
        for (int r = 0; r < 8; ++r) {
            float4 kd4 = *(const float4*)&ks[r][d0];
            float4 ve4 = *(const float4*)&vs[r][e0];
            float kd[4] = {kd4.x, kd4.y, kd4.z, kd4.w};
            float ve[4] = {ve4.x, ve4.y, ve4.z, ve4.w};
#pragma unroll
            for (int i = 0; i < 4; ++i)
#pragma unroll
                for (int j = 0; j < 4; ++j)
                    acc[i][j] = fmaf(kd[i], ve[j], acc[i][j]);
            if (eg == 0) {
#pragma unroll
                for (int i = 0; i < 4; ++i) sacc[i] += kd[i];
            }
        }
        __syncthreads();
    }

    float* kvp = g_kv + (size_t)bh * HDIM * HDIM;
#pragma unroll
    for (int i = 0; i < 4; ++i)
#pragma unroll
        for (int j = 0; j < 4; ++j)
            atomicAdd(&kvp[(d0 + i) * HDIM + e0 + j], acc[i][j]);
    if (eg == 0) {
#pragma unroll
        for (int i = 0; i < 4; ++i)
            atomicAdd(&g_ksum[bh * HDIM + d0 + i], sacc[i]);
    }
}

// ---------------- attended = (qf @ kv) / max(qf . ksum, eps) -----------------
__global__ __launch_bounds__(256)
void attend_kernel()
{
    const int tile = blockIdx.x;
    const int bh = blockIdx.y;
    const int b = bh >> 4, h = bh & 15;
    const int row0 = b * SEQ + tile * 64;

    __shared__ __align__(16) float kvs[64][64];
    __shared__ __align__(16) float qs[64][64];
    __shared__ float ksum_s[64];

    const int tid = threadIdx.x;

    const float* kvp = g_kv + (size_t)bh * HDIM * HDIM;
    for (int i = tid; i < 1024; i += 256)
        ((float4*)kvs)[i] = ((const float4*)kvp)[i];
    if (tid < 64) ksum_s[tid] = g_ksum[bh * HDIM + tid];

    const float* Qp = g_q + (size_t)row0 * D_MODEL + h * HDIM;
    for (int i = tid; i < 1024; i += 256) {
        const int r = i >> 4, c = (i & 15) * 4;
        *(float4*)&qs[r][c] = *(const float4*)(Qp + (size_t)r * D_MODEL + c);
    }
    __syncthreads();

    const int cg = tid & 15, rg = tid >> 4;
    const int c0 = cg * 4, r0 = rg * 4;

    float num[4][4];
#pragma unroll
    for (int i = 0; i < 4; ++i)
#pragma unroll
        for (int j = 0; j < 4; ++j) num[i][j] = 0.f;
    float den[4] = {0.f, 0.f, 0.f, 0.f};

    for (int d = 0; d < 64; ++d) {
        float qv[4];
#pragma unroll
        for (int i = 0; i < 4; ++i) qv[i] = qs[r0 + i][d];
        float4 kv4 = *(const float4*)&kvs[d][c0];
        float kva[4] = {kv4.x, kv4.y, kv4.z, kv4.w};
        const float kd = ksum_s[d];
#pragma unroll
        for (int i = 0; i < 4; ++i) {
#pragma unroll
            for (int j = 0; j < 4; ++j)
                num[i][j] = fmaf(qv[i], kva[j], num[i][j]);
            den[i] = fmaf(qv[i], kd, den[i]);
        }
    }

#pragma unroll
    for (int i = 0; i < 4; ++i) {
        const float inv = 1.f / fmaxf(den[i], EPS_V);
        float4 res = make_float4(num[i][0] * inv, num[i][1] * inv,
                                 num[i][2] * inv, num[i][3] * inv);
        u32 h0, h1, l0, l1;
        split4(res, h0, h1, l0, l1);
        const size_t e4 = ((size_t)(row0 + r0 + i) * D_MODEL + h * HDIM + c0) >> 2;
        ((uint2*)g_oh)[e4] = make_uint2(h0, h1);
        ((uint2*)g_ol)[e4] = make_uint2(l0, l1);
    }
}

// ---------------- launch -----------------------------------------------------
extern "C" void kernel_launch(void* const* d_in, const int* in_sizes, int n_in,
                              void* d_out, int out_size)
{
    const float* x  = (const float*)d_in[0];
    const float* wq = (const float*)d_in[1];
    const float* bq = (const float*)d_in[2];
    const float* wk = (const float*)d_in[3];
    const float* bk = (const float*)d_in[4];
    const float* wv = (const float*)d_in[5];
    const float* bv = (const float*)d_in[6];
    const float* wo = (const float*)d_in[7];
    const float* bo = (const float*)d_in[8];
    float* out = (float*)d_out;

    const int M = in_sizes[0] / D_MODEL;   // 4096

    float *qp, *kp, *vp;
    u16 *xh, *xl, *oh, *ol, *wh, *wl;
    cudaGetSymbolAddress((void**)&qp, g_q);
    cudaGetSymbolAddress((void**)&kp, g_k);
    cudaGetSymbolAddress((void**)&vp, g_v);
    cudaGetSymbolAddress((void**)&xh, g_xh);
    cudaGetSymbolAddress((void**)&xl, g_xl);
    cudaGetSymbolAddress((void**)&oh, g_oh);
    cudaGetSymbolAddress((void**)&ol, g_ol);
    cudaGetSymbolAddress((void**)&wh, g_wh);
    cudaGetSymbolAddress((void**)&wl, g_wl);

    cudaFuncSetAttribute(gemm3s, cudaFuncAttributeMaxDynamicSharedMemorySize, GEMM_SMEM);

    // 1,2: conversion passes
    split_x_kernel<<<(M * D_MODEL / 4) / 256, 256>>>(x);
    split_w_kernel<<<dim3((D_MODEL * D_MODEL / 4) / 256, 4), 256>>>(wq, wk, wv, wo);
    // 3: zero accumulators
    zero_kv_kernel<<<(NBATCH * NHEAD * HDIM * HDIM + 255) / 256, 256>>>();

    // 4: fused QKV projection, N=3072 over packed weights (profiled launch)
    gemm3s<<<dim3(3 * D_MODEL / BN, M / BM), 256, GEMM_SMEM>>>(
        xh, xl, wh, wl,
        bq, bk, bv, qp, kp, vp,
        M, D_MODEL, 0b011);

    // 5,6: linear-attention middle
    kv_kernel<<<dim3(NBATCH * NHEAD, 8), 256>>>();
    attend_kernel<<<dim3(SEQ / 64, NBATCH * NHEAD), 256>>>();

    // 7: output projection (wo rows start at 3*D*D)
    gemm3s<<<dim3(D_MODEL / BN, M / BM), 256, GEMM_SMEM>>>(
        oh, ol,
        wh + (size_t)3 * D_MODEL * D_MODEL, wl + (size_t)3 * D_MODEL * D_MODEL,
        bo, bo, bo, out, out, out,
        M, D_MODEL, 0);
}

// round 6
// speedup vs baseline: 2.8282x; 1.0233x over previous
#include <cuda_runtime.h>
#include <cuda_bf16.h>
#include <cstdint>
#include <math.h>

#define D_MODEL 1024
#define NHEAD 16
#define HDIM 64
#define SEQ 2048
#define NBATCH 2
#define NROWS (NBATCH * SEQ)          // 4096
#define EPS_V 1e-6f

typedef uint16_t u16;
typedef uint32_t u32;

// ---------------- scratch (device globals; no allocation allowed) -----------
__device__ float g_q[NROWS * D_MODEL];
__device__ float g_k[NROWS * D_MODEL];
__device__ float g_v[NROWS * D_MODEL];
__device__ float g_kv[NBATCH * NHEAD * HDIM * HDIM];
__device__ float g_ksum[NBATCH * NHEAD * HDIM];

// bf16 split planes
__device__ __align__(16) u16 g_xh[NROWS * D_MODEL];
__device__ __align__(16) u16 g_xl[NROWS * D_MODEL];
__device__ __align__(16) u16 g_oh[NROWS * D_MODEL];
__device__ __align__(16) u16 g_ol[NROWS * D_MODEL];
// packed weights: rows [0,1024)=wq, [1024,2048)=wk, [2048,3072)=wv, [3072,4096)=wo
__device__ __align__(16) u16 g_wh[4 * D_MODEL * D_MODEL];
__device__ __align__(16) u16 g_wl[4 * D_MODEL * D_MODEL];

__device__ __forceinline__ u32 smem_u32(const void* p) {
    u32 a;
    asm("{ .reg .u64 t; cvta.to.shared.u64 t, %1; cvt.u32.u64 %0, t; }"
        : "=r"(a) : "l"(p));
    return a;
}

__device__ __forceinline__ void ldsm4(u32* r, u32 addr) {
    asm volatile("ldmatrix.sync.aligned.m8n8.x4.shared.b16 {%0,%1,%2,%3}, [%4];"
                 : "=r"(r[0]), "=r"(r[1]), "=r"(r[2]), "=r"(r[3]) : "r"(addr));
}

__device__ __forceinline__ void mma16816(float* c, const u32* a, u32 b0, u32 b1) {
    asm volatile(
        "mma.sync.aligned.m16n8k16.row.col.f32.bf16.bf16.f32 "
        "{%0,%1,%2,%3}, {%4,%5,%6,%7}, {%8,%9}, {%0,%1,%2,%3};"
        : "+f"(c[0]), "+f"(c[1]), "+f"(c[2]), "+f"(c[3])
        : "r"(a[0]), "r"(a[1]), "r"(a[2]), "r"(a[3]), "r"(b0), "r"(b1));
}

#define CP16(dst, src) \
    asm volatile("cp.async.cg.shared.global [%0], [%1], 16;" :: "r"(dst), "l"(src))
#define CP_COMMIT() asm volatile("cp.async.commit_group;" ::: "memory")
#define CP_WAIT0()  asm volatile("cp.async.wait_group 0;" ::: "memory")
#define CP_WAIT1()  asm volatile("cp.async.wait_group 1;" ::: "memory")

__device__ __forceinline__ void split4(float4 f, u32& h0, u32& h1, u32& l0, u32& l1) {
    u32 bx = __float_as_uint(f.x), by = __float_as_uint(f.y);
    u32 bz = __float_as_uint(f.z), bw = __float_as_uint(f.w);
    h0 = __byte_perm(bx, by, 0x7632);
    h1 = __byte_perm(bz, bw, 0x7632);
    float lx = f.x - __uint_as_float(bx & 0xFFFF0000u);
    float ly = f.y - __uint_as_float(by & 0xFFFF0000u);
    float lz = f.z - __uint_as_float(bz & 0xFFFF0000u);
    float lw = f.w - __uint_as_float(bw & 0xFFFF0000u);
    asm("cvt.rn.bf16x2.f32 %0, %1, %2;" : "=r"(l0) : "f"(ly), "f"(lx));
    asm("cvt.rn.bf16x2.f32 %0, %1, %2;" : "=r"(l1) : "f"(lw), "f"(lz));
}

// ---------------- conversion passes -----------------------------------------
__global__ __launch_bounds__(256) void split_x_kernel(const float* __restrict__ src)
{
    const int i = blockIdx.x * 256 + threadIdx.x;
    float4 f = ((const float4*)src)[i];
    u32 h0, h1, l0, l1;
    split4(f, h0, h1, l0, l1);
    ((uint2*)g_xh)[i] = make_uint2(h0, h1);
    ((uint2*)g_xl)[i] = make_uint2(l0, l1);
}

__global__ __launch_bounds__(256) void split_w_kernel(
    const float* __restrict__ w0, const float* __restrict__ w1,
    const float* __restrict__ w2, const float* __restrict__ w3)
{
    const int m = blockIdx.y;
    const float* src = (m == 0) ? w0 : (m == 1) ? w1 : (m == 2) ? w2 : w3;
    const size_t i = blockIdx.x * 256 + threadIdx.x;
    float4 f = ((const float4*)src)[i];
    u32 h0, h1, l0, l1;
    split4(f, h0, h1, l0, l1);
    const size_t o = (size_t)m * (D_MODEL * D_MODEL / 4) + i;
    ((uint2*)g_wh)[o] = make_uint2(h0, h1);
    ((uint2*)g_wl)[o] = make_uint2(l0, l1);
}

// ======================= bf16 3-term split GEMM ==============================
// BM=128, BN=256. 8 warps (2M x 4N), warp tile 64x64. 2-stage cp.async.
// smem/stage: Ah(16K) Al(16K) Wh(32K) Wl(32K) = 96KB; 2 stages = 192KB.
#define BM 128
#define BN 256
#define APLANE_B 16384
#define WPLANE_B 32768
#define STAGE_B (2 * APLANE_B + 2 * WPLANE_B)    // 98304
#define GEMM_SMEM (2 * STAGE_B)                  // 196608

__global__ __launch_bounds__(256, 1)
void gemm3s(const u16* __restrict__ Ah, const u16* __restrict__ Al,
            const u16* __restrict__ Wh, const u16* __restrict__ Wl,
            const float* __restrict__ b0, const float* __restrict__ b1,
            const float* __restrict__ b2,
            float* __restrict__ C0, float* __restrict__ C1, float* __restrict__ C2,
            int M, int K, int actmask)
{
    extern __shared__ __align__(1024) char smem[];
    const u32 sb = smem_u32(smem);

    const int tid = threadIdx.x;
    const int lane = tid & 31, wid = tid >> 5;
    const int wm = wid >> 2, wn = wid & 3;
    const int bm = blockIdx.y * BM;
    const int bng = blockIdx.x * BN;          // global col in packed weight
    const int seg = blockIdx.x >> 2;          // 1024/BN = 4 tiles per segment
    const int bns = bng & 1023;               // col within segment

    const float* bias = (seg == 0) ? b0 : (seg == 1) ? b1 : b2;
    float* C = (seg == 0) ? C0 : (seg == 1) ? C1 : C2;
    const int act = (actmask >> seg) & 1;

    const int NCH = K / 64;

    // ---- ldmatrix addressing ----
    const int arow_l = (lane & 15);
    const u32 akb = (u32)((lane >> 4) * 16);
    const int brow_l = (lane & 7) + ((lane >> 4) << 3);
    const u32 bkb = (u32)(((lane >> 3) & 1) * 16);

    u32 abase[4], axor[4];
#pragma unroll
    for (int mt = 0; mt < 4; ++mt) {
        const int r = wm * 64 + mt * 16 + arow_l;
        abase[mt] = (u32)(r * 128);
        axor[mt] = (u32)((r & 7) << 4);
    }
    u32 bbase[4], bxor[4];
#pragma unroll
    for (int p = 0; p < 4; ++p) {
        const int r = wn * 64 + p * 16 + brow_l;
        bbase[p] = (u32)(r * 128);
        bxor[p] = (u32)((r & 7) << 4);
    }

    float acc[4][8][4];
#pragma unroll
    for (int i = 0; i < 4; ++i)
#pragma unroll
        for (int j = 0; j < 8; ++j)
#pragma unroll
            for (int d = 0; d < 4; ++d) acc[i][j][d] = 0.f;

    // loader: A planes 2048 16B-chunks, W planes 4096; total 6144 = 24/thread
    auto load_chunk = [&](int c, int stage) {
        const u32 bufb = sb + stage * STAGE_B;
        const size_t kc = (size_t)c * 64;
        // A planes: 128 rows x 8 chunks, 4 iters
#pragma unroll
        for (int i = 0; i < 4; ++i) {
            const int idx = i * 256 + tid;
            const int r = idx >> 3, c16 = idx & 7;
            const u32 dsto = (u32)(r * 128 + ((c16 * 16) ^ ((r & 7) * 16)));
            const size_t asrc = (size_t)(bm + r) * K + kc + c16 * 8;
            CP16(bufb + dsto, Ah + asrc);
            CP16(bufb + APLANE_B + dsto, Al + asrc);
        }
        // W planes: 256 rows x 8 chunks, 8 iters
        const u32 wb = bufb + 2 * APLANE_B;
#pragma unroll
        for (int i = 0; i < 8; ++i) {
            const int idx = i * 256 + tid;
            const int r = idx >> 3, c16 = idx & 7;
            const u32 dsto = (u32)(r * 128 + ((c16 * 16) ^ ((r & 7) * 16)));
            const size_t wsrc = (size_t)(bng + r) * K + kc + c16 * 8;
            CP16(wb + dsto, Wh + wsrc);
            CP16(wb + WPLANE_B + dsto, Wl + wsrc);
        }
        CP_COMMIT();
    };

    load_chunk(0, 0);

    for (int c = 0; c < NCH; ++c) {
        if (c + 1 < NCH) {
            load_chunk(c + 1, (c + 1) & 1);
            CP_WAIT1();
        } else {
            CP_WAIT0();
        }
        __syncthreads();

        const u32 bufb = sb + (c & 1) * STAGE_B;
        const u32 AHb = bufb, ALb = bufb + APLANE_B;
        const u32 WHb = bufb + 2 * APLANE_B, WLb = WHb + WPLANE_B;

#pragma unroll
        for (int ks = 0; ks < 4; ++ks) {
            u32 ah[4][4], al[4][4], bh[4][4], bl[4][4];
#pragma unroll
            for (int mt = 0; mt < 4; ++mt) {
                const u32 t = ((u32)(ks * 32) + akb) ^ axor[mt];
                ldsm4(ah[mt], AHb + abase[mt] + t);
                ldsm4(al[mt], ALb + abase[mt] + t);
            }
#pragma unroll
            for (int p = 0; p < 4; ++p) {
                const u32 t = ((u32)(ks * 32) + bkb) ^ bxor[p];
                ldsm4(bh[p], WHb + bbase[p] + t);
                ldsm4(bl[p], WLb + bbase[p] + t);
            }
            // term-outer: 32 independent mmas between same-acc writes
#pragma unroll
            for (int mt = 0; mt < 4; ++mt)
#pragma unroll
                for (int nt = 0; nt < 8; ++nt) {
                    const int p = nt >> 1, q = (nt & 1) * 2;
                    mma16816(acc[mt][nt], ah[mt], bh[p][q], bh[p][q + 1]);
                }
#pragma unroll
            for (int mt = 0; mt < 4; ++mt)
#pragma unroll
                for (int nt = 0; nt < 8; ++nt) {
                    const int p = nt >> 1, q = (nt & 1) * 2;
                    mma16816(acc[mt][nt], ah[mt], bl[p][q], bl[p][q + 1]);
                }
#pragma unroll
            for (int mt = 0; mt < 4; ++mt)
#pragma unroll
                for (int nt = 0; nt < 8; ++nt) {
                    const int p = nt >> 1, q = (nt & 1) * 2;
                    mma16816(acc[mt][nt], al[mt], bh[p][q], bh[p][q + 1]);
                }
        }
        __syncthreads();
    }

    // ---- epilogue ----
    const int erow = bm + wm * 64 + (lane >> 2);
    const int ecol0 = bns + wn * 64 + (lane & 3) * 2;
#pragma unroll
    for (int nt = 0; nt < 8; ++nt) {
        const int col = ecol0 + nt * 8;
        const float bb0 = bias[col], bb1 = bias[col + 1];
#pragma unroll
        for (int mt = 0; mt < 4; ++mt) {
#pragma unroll
            for (int h = 0; h < 2; ++h) {
                const int row = erow + mt * 16 + h * 8;
                float v0 = acc[mt][nt][2 * h] + bb0;
                float v1 = acc[mt][nt][2 * h + 1] + bb1;
                if (act) {
                    v0 = (v0 > 0.f) ? (v0 + 1.f) : __expf(v0);
                    v1 = (v1 > 0.f) ? (v1 + 1.f) : __expf(v1);
                }
                *(float2*)(C + (size_t)row * D_MODEL + col) = make_float2(v0, v1);
            }
        }
    }
}

// ---------------- zero the kv / ksum accumulators ---------------------------
__global__ void zero_kv_kernel()
{
    const int i = blockIdx.x * blockDim.x + threadIdx.x;
    if (i < NBATCH * NHEAD * HDIM * HDIM) g_kv[i] = 0.f;
    if (i < NBATCH * NHEAD * HDIM)        g_ksum[i] = 0.f;
}

// ---------------- kv = kf^T @ v per (b,h), split-K over sequence ------------
__global__ __launch_bounds__(256)
void kv_kernel()
{
    const int bh = blockIdx.x;
    const int split = blockIdx.y;
    const int b = bh >> 4, h = bh & 15;
    const int j0 = b * SEQ + split * 256;

    const float* Kp = g_k + (size_t)j0 * D_MODEL + h * HDIM;
    const float* Vp = g_v + (size_t)j0 * D_MODEL + h * HDIM;

    __shared__ __align__(16) float ks[8][64];
    __shared__ __align__(16) float vs[8][64];

    const int tid = threadIdx.x;
    const int eg = tid & 15, dg = tid >> 4;
    const int e0 = eg * 4, d0 = dg * 4;

    float acc[4][4];
#pragma unroll
    for (int i = 0; i < 4; ++i)
#pragma unroll
        for (int j = 0; j < 4; ++j) acc[i][j] = 0.f;
    float sacc[4] = {0.f, 0.f, 0.f, 0.f};

    for (int it = 0; it < 32; ++it) {
        const int rbase = it * 8;
        if (tid < 128) {
            const int r = tid >> 4, c = (tid & 15) * 4;
            *(float4*)&ks[r][c] = *(const float4*)(Kp + (size_t)(rbase + r) * D_MODEL + c);
        } else {
            const int t = tid - 128;
            const int r = t >> 4, c = (t & 15) * 4;
            *(float4*)&vs[r][c] = *(const float4*)(Vp + (size_t)(rbase + r) * D_MODEL + c);
        }
        __syncthreads();
#pragma unroll
        for (int r = 0; r < 8; ++r) {
            float4 kd4 = *(const float4*)&ks[r][d0];
            float4 ve4 = *(const float4*)&vs[r][e0];
            float kd[4] = {kd4.x, kd4.y, kd4.z, kd4.w};
            float ve[4] = {ve4.x, ve4.y, ve4.z, ve4.w};
#pragma unroll
            for (int i = 0; i < 4; ++i)
#pragma unroll
                for (int j = 0; j < 4; ++j)
                    acc[i][j] = fmaf(kd[i], ve[j], acc[i][j]);
            if (eg == 0) {
#pragma unroll
                for (int i = 0; i < 4; ++i) sacc[i] += kd[i];
            }
        }
        __syncthreads();
    }

    float* kvp = g_kv + (size_t)bh * HDIM * HDIM;
#pragma unroll
    for (int i = 0; i < 4; ++i)
#pragma unroll
        for (int j = 0; j < 4; ++j)
            atomicAdd(&kvp[(d0 + i) * HDIM + e0 + j], acc[i][j]);
    if (eg == 0) {
#pragma unroll
        for (int i = 0; i < 4; ++i)
            atomicAdd(&g_ksum[bh * HDIM + d0 + i], sacc[i]);
    }
}

// ---------------- attended = (qf @ kv) / max(qf . ksum, eps) -----------------
__global__ __launch_bounds__(256)
void attend_kernel()
{
    const int tile = blockIdx.x;
    const int bh = blockIdx.y;
    const int b = bh >> 4, h = bh & 15;
    const int row0 = b * SEQ + tile * 64;

    __shared__ __align__(16) float kvs[64][64];
    __shared__ __align__(16) float qs[64][64];
    __shared__ float ksum_s[64];

    const int tid = threadIdx.x;

    const float* kvp = g_kv + (size_t)bh * HDIM * HDIM;
    for (int i = tid; i < 1024; i += 256)
        ((float4*)kvs)[i] = ((const float4*)kvp)[i];
    if (tid < 64) ksum_s[tid] = g_ksum[bh * HDIM + tid];

    const float* Qp = g_q + (size_t)row0 * D_MODEL + h * HDIM;
    for (int i = tid; i < 1024; i += 256) {
        const int r = i >> 4, c = (i & 15) * 4;
        *(float4*)&qs[r][c] = *(const float4*)(Qp + (size_t)r * D_MODEL + c);
    }
    __syncthreads();

    const int cg = tid & 15, rg = tid >> 4;
    const int c0 = cg * 4, r0 = rg * 4;

    float num[4][4];
#pragma unroll
    for (int i = 0; i < 4; ++i)
#pragma unroll
        for (int j = 0; j < 4; ++j) num[i][j] = 0.f;
    float den[4] = {0.f, 0.f, 0.f, 0.f};

    for (int d = 0; d < 64; ++d) {
        float qv[4];
#pragma unroll
        for (int i = 0; i < 4; ++i) qv[i] = qs[r0 + i][d];
        float4 kv4 = *(const float4*)&kvs[d][c0];
        float kva[4] = {kv4.x, kv4.y, kv4.z, kv4.w};
        const float kd = ksum_s[d];
#pragma unroll
        for (int i = 0; i < 4; ++i) {
#pragma unroll
            for (int j = 0; j < 4; ++j)
                num[i][j] = fmaf(qv[i], kva[j], num[i][j]);
            den[i] = fmaf(qv[i], kd, den[i]);
        }
    }

#pragma unroll
    for (int i = 0; i < 4; ++i) {
        const float inv = 1.f / fmaxf(den[i], EPS_V);
        float4 res = make_float4(num[i][0] * inv, num[i][1] * inv,
                                 num[i][2] * inv, num[i][3] * inv);
        u32 h0, h1, l0, l1;
        split4(res, h0, h1, l0, l1);
        const size_t e4 = ((size_t)(row0 + r0 + i) * D_MODEL + h * HDIM + c0) >> 2;
        ((uint2*)g_oh)[e4] = make_uint2(h0, h1);
        ((uint2*)g_ol)[e4] = make_uint2(l0, l1);
    }
}

// ---------------- launch -----------------------------------------------------
extern "C" void kernel_launch(void* const* d_in, const int* in_sizes, int n_in,
                              void* d_out, int out_size)
{
    const float* x  = (const float*)d_in[0];
    const float* wq = (const float*)d_in[1];
    const float* bq = (const float*)d_in[2];
    const float* wk = (const float*)d_in[3];
    const float* bk = (const float*)d_in[4];
    const float* wv = (const float*)d_in[5];
    const float* bv = (const float*)d_in[6];
    const float* wo = (const float*)d_in[7];
    const float* bo = (const float*)d_in[8];
    float* out = (float*)d_out;

    const int M = in_sizes[0] / D_MODEL;   // 4096

    float *qp, *kp, *vp;
    u16 *xh, *xl, *oh, *ol, *wh, *wl;
    cudaGetSymbolAddress((void**)&qp, g_q);
    cudaGetSymbolAddress((void**)&kp, g_k);
    cudaGetSymbolAddress((void**)&vp, g_v);
    cudaGetSymbolAddress((void**)&xh, g_xh);
    cudaGetSymbolAddress((void**)&xl, g_xl);
    cudaGetSymbolAddress((void**)&oh, g_oh);
    cudaGetSymbolAddress((void**)&ol, g_ol);
    cudaGetSymbolAddress((void**)&wh, g_wh);
    cudaGetSymbolAddress((void**)&wl, g_wl);

    cudaFuncSetAttribute(gemm3s, cudaFuncAttributeMaxDynamicSharedMemorySize, GEMM_SMEM);

    // 1,2: conversion passes
    split_x_kernel<<<(M * D_MODEL / 4) / 256, 256>>>(x);
    split_w_kernel<<<dim3((D_MODEL * D_MODEL / 4) / 256, 4), 256>>>(wq, wk, wv, wo);
    // 3: zero accumulators
    zero_kv_kernel<<<(NBATCH * NHEAD * HDIM * HDIM + 255) / 256, 256>>>();

    // 4: fused QKV projection, N=3072 over packed weights (profiled launch)
    gemm3s<<<dim3(3 * D_MODEL / BN, M / BM), 256, GEMM_SMEM>>>(
        xh, xl, wh, wl,
        bq, bk, bv, qp, kp, vp,
        M, D_MODEL, 0b011);

    // 5,6: linear-attention middle
    kv_kernel<<<dim3(NBATCH * NHEAD, 8), 256>>>();
    attend_kernel<<<dim3(SEQ / 64, NBATCH * NHEAD), 256>>>();

    // 7: output projection (wo rows start at 3*D*D)
    gemm3s<<<dim3(D_MODEL / BN, M / BM), 256, GEMM_SMEM>>>(
        oh, ol,
        wh + (size_t)3 * D_MODEL * D_MODEL, wl + (size_t)3 * D_MODEL * D_MODEL,
        bo, bo, bo, out, out, out,
        M, D_MODEL, 0);
}